// round 15
// baseline (speedup 1.0000x reference)
#include <cuda_runtime.h>
#include <cuda_bf16.h>
#include <float.h>
#include <math.h>
#include <stdint.h>

// Problem constants (fixed by the reference)
#define Nn 50000
#define Ee 600000
#define ET (Ee + Nn)     // edges + self loops = 650000 (even)
#define D  128
#define Bb 1024
#define BN_EPS 1e-5f
#define AGG_NPW 4        // nodes per warp in aggregation
#define TROWS 64         // GEMM tile rows
#define NTILES ((Nn + TROWS - 1) / TROWS)   // 782
#define GEMM_GRID (NTILES / 2)              // 391, 2 tiles per CTA

// ---------------- static device scratch ----------------
__device__ float g_bufA[Nn * D];      // GEMM output h (fp32)
__device__ float g_bufB[Nn * D];      // aggregated output
__device__ float g_si[Nn], g_sj[Nn];
__device__ float g_den[Nn];           // sum of exp per src node (raw)
__device__ float g_alpha[ET];         // exp(alpha), CSR-position order
__device__ int   g_srcpos[ET];
__device__ int   g_dstpos[ET];
__device__ int   g_deg[Nn];
__device__ int   g_off[Nn + 1];
__device__ int   g_cur[Nn];
__device__ float g_bnsum[D], g_bnsq[D];
__device__ float g_M[D * D];
// padded-row bf16 split images of W for all 3 layers: [3][2048] uint4 each
__device__ uint4 g_WhiAll[3 * 2048];
__device__ uint4 g_WloAll[3 * 2048];

// ---------------- PTX helpers (plain compute_103-safe) ----------------
__device__ __forceinline__ uint32_t smem_u32(const void* p) {
    uint32_t a;
    asm("{ .reg .u64 t; cvta.to.shared.u64 t, %1; cvt.u32.u64 %0, t; }" : "=r"(a) : "l"(p));
    return a;
}

__device__ __forceinline__ void ldmx4(uint32_t* r, uint32_t addr) {
    asm volatile("ldmatrix.sync.aligned.m8n8.x4.shared.b16 {%0,%1,%2,%3}, [%4];"
                 : "=r"(r[0]), "=r"(r[1]), "=r"(r[2]), "=r"(r[3]) : "r"(addr));
}

__device__ __forceinline__ void mma16816(float* c, const uint32_t* a, uint32_t b0, uint32_t b1) {
    asm volatile(
        "mma.sync.aligned.m16n8k16.row.col.f32.bf16.bf16.f32 "
        "{%0,%1,%2,%3}, {%4,%5,%6,%7}, {%8,%9}, {%0,%1,%2,%3};"
        : "+f"(c[0]), "+f"(c[1]), "+f"(c[2]), "+f"(c[3])
        : "r"(a[0]), "r"(a[1]), "r"(a[2]), "r"(a[3]), "r"(b0), "r"(b1));
}

// ---------------- CSR build (by dst) ----------------
__device__ __forceinline__ int edge_src(const int* ei, int e) {
    return (e < Ee) ? ei[e] : (e - Ee);
}
__device__ __forceinline__ int edge_dst(const int* ei, int e) {
    return (e < Ee) ? ei[Ee + e] : (e - Ee);
}

__global__ void k_count(const int* __restrict__ ei) {
    int e = blockIdx.x * blockDim.x + threadIdx.x;
    if (e >= ET) return;
    atomicAdd(&g_deg[edge_dst(ei, e)], 1);
}

__global__ void k_scan() {
    __shared__ int part[1024];
    int tid = threadIdx.x;
    const int CH = (Nn + 1023) / 1024;
    int base = tid * CH;
    int s = 0;
    for (int i = 0; i < CH; i++) {
        int idx = base + i;
        if (idx < Nn) s += g_deg[idx];
    }
    part[tid] = s;
    __syncthreads();
    for (int d = 1; d < 1024; d <<= 1) {
        int v = (tid >= d) ? part[tid - d] : 0;
        __syncthreads();
        part[tid] += v;
        __syncthreads();
    }
    int run = (tid > 0) ? part[tid - 1] : 0;
    for (int i = 0; i < CH; i++) {
        int idx = base + i;
        if (idx < Nn) {
            g_off[idx] = run;
            g_cur[idx] = run;
            run += g_deg[idx];
        }
    }
    if (tid == 1023) g_off[Nn] = part[1023];
}

__global__ void k_scatter(const int* __restrict__ ei) {
    int e = blockIdx.x * blockDim.x + threadIdx.x;
    if (e >= ET) return;
    int s = edge_src(ei, e);
    int d = edge_dst(ei, e);
    int pos = atomicAdd(&g_cur[d], 1);
    g_srcpos[pos] = s;
    g_dstpos[pos] = d;
}

#define SROW 272

// ---------------- W split: fp32 -> padded-row bf16 hi/lo images (all 3 layers) -------
__global__ void k_wsplit_all(const float* __restrict__ W0, const float* __restrict__ W1,
                             const float* __restrict__ W2) {
    int id = blockIdx.x * blockDim.x + threadIdx.x;  // 0..6143
    if (id >= 3 * 2048) return;
    int L = id >> 11;
    int idx = id & 2047;
    const float* W = (L == 0) ? W0 : (L == 1) ? W1 : W2;
    int n = idx >> 4;           // row (out channel)
    int k0 = (idx & 15) * 8;    // 8 consecutive k
    const float* src = W + n * 128 + k0;
    float v[8];
#pragma unroll
    for (int j = 0; j < 8; j++) v[j] = src[j];
    uint32_t hi[4], lo[4];
#pragma unroll
    for (int j = 0; j < 4; j++) {
        __nv_bfloat162 hp = __floats2bfloat162_rn(v[2 * j], v[2 * j + 1]);
        float2 hf = __bfloat1622float2(hp);
        __nv_bfloat162 lp = __floats2bfloat162_rn(v[2 * j] - hf.x, v[2 * j + 1] - hf.y);
        hi[j] = *reinterpret_cast<uint32_t*>(&hp);
        lo[j] = *reinterpret_cast<uint32_t*>(&lp);
    }
    g_WhiAll[id] = make_uint4(hi[0], hi[1], hi[2], hi[3]);
    g_WloAll[id] = make_uint4(lo[0], lo[1], lo[2], lo[3]);
}

// ---------------- HMMA GEMM: C = A' @ W^T, 2 tiles per CTA, 2 CTAs/SM ----------------
#define SME_ATT  0
#define SME_SC   1024
#define SME_SH   1536
#define SME_REDI 2048
#define SME_REDJ 3072
#define SME_AHI  4096
#define SME_ALO  (SME_AHI + TROWS * SROW)
#define SME_WHI  (SME_ALO + TROWS * SROW)
#define SME_WLO  (SME_WHI + 128 * SROW)
#define SME_TOTAL (SME_WLO + 128 * SROW)   // 108544 B -> 2 CTAs/SM

template <bool BN>
__global__ void __launch_bounds__(256, 2)
k_gemm_mma(const float* __restrict__ A, const float* __restrict__ att,
           const float* __restrict__ gamma, const float* __restrict__ beta,
           const uint4* __restrict__ whiG, const uint4* __restrict__ wloG,
           float* __restrict__ C, int Mrows) {
    extern __shared__ char smem[];
    uint32_t sb = smem_u32(smem);
    int tid = threadIdx.x;
    int wid = tid >> 5;
    int lane = tid & 31;
    int warpM = wid & 1;   // 0..1, 32 rows each
    int warpN = wid >> 1;  // 0..3, 32 cols each

    float* attS = (float*)(smem + SME_ATT);
    float* scS  = (float*)(smem + SME_SC);
    float* shS  = (float*)(smem + SME_SH);
    float* redI = (float*)(smem + SME_REDI);
    float* redJ = (float*)(smem + SME_REDJ);

    if (tid < 256) attS[tid] = att[tid];
    if (BN && tid < 128) {
        const float invN = 1.f / (float)Nn;
        float mu = g_bnsum[tid] * invN;
        float var = g_bnsq[tid] * invN - mu * mu;
        float sc = rsqrtf(var + BN_EPS) * gamma[tid];
        scS[tid] = sc;
        shS[tid] = beta[tid] - mu * sc;
    }

    // copy padded W images into smem (once per CTA, reused across tiles)
    for (int i = tid; i < 2048; i += 256) {
        int r = i >> 4;
        int c = i & 15;
        *(uint4*)(smem + SME_WHI + r * SROW + c * 16) = whiG[i];
        *(uint4*)(smem + SME_WLO + r * SROW + c * 16) = wloG[i];
    }
    __syncthreads();   // W + BN coefficients ready

    // lane-invariant addressing
    int a_row = lane & 15;
    int a_k   = (lane >> 4) * 8;
    uint32_t aLaneOff = a_row * SROW + a_k * 2;
    int b_n = (lane & 7) + ((lane >> 4) << 3);
    int b_k = ((lane >> 3) & 1) * 8;
    uint32_t bLaneOff = b_n * SROW + b_k * 2;
    uint32_t aBaseHi = sb + SME_AHI + (warpM * 32) * SROW + aLaneOff;
    uint32_t aBaseLo = sb + SME_ALO + (warpM * 32) * SROW + aLaneOff;
    uint32_t bBaseH  = sb + SME_WHI + (warpN * 32) * SROW + bLaneOff;
    uint32_t bBaseL  = sb + SME_WLO + (warpN * 32) * SROW + bLaneOff;

    for (int tile = blockIdx.x; tile < NTILES; tile += gridDim.x) {
        int block_row = tile * TROWS;

        // convert A tile (64 rows) -> bf16 hi/lo (padded rows)
        {
            int r = tid >> 2;               // 0..63
            int kq = (tid & 3) * 32;        // quarter-row
            int grow = block_row + r;
            bool valid = (grow < Mrows);
            const float* arow = A + (size_t)grow * 128 + kq;
#pragma unroll
            for (int c = 0; c < 4; c++) {   // 4 chunks of 8 floats
                int k0 = kq + c * 8;
                float v[8];
                if (valid) {
                    float4 p0 = *(const float4*)(arow + c * 8);
                    float4 p1 = *(const float4*)(arow + c * 8 + 4);
                    v[0] = p0.x; v[1] = p0.y; v[2] = p0.z; v[3] = p0.w;
                    v[4] = p1.x; v[5] = p1.y; v[6] = p1.z; v[7] = p1.w;
                } else {
#pragma unroll
                    for (int j = 0; j < 8; j++) v[j] = 0.f;
                }
                if (BN) {
#pragma unroll
                    for (int j = 0; j < 8; j++) {
                        float y = v[j] * scS[k0 + j] + shS[k0 + j];
                        v[j] = (y > 0.f) ? y : 0.1f * y;
                    }
                }
                uint32_t hi[4], lo[4];
#pragma unroll
                for (int j = 0; j < 4; j++) {
                    __nv_bfloat162 hp = __floats2bfloat162_rn(v[2 * j], v[2 * j + 1]);
                    float2 hf = __bfloat1622float2(hp);
                    __nv_bfloat162 lp = __floats2bfloat162_rn(v[2 * j] - hf.x, v[2 * j + 1] - hf.y);
                    hi[j] = *reinterpret_cast<uint32_t*>(&hp);
                    lo[j] = *reinterpret_cast<uint32_t*>(&lp);
                }
                *(uint4*)(smem + SME_AHI + r * SROW + k0 * 2) = make_uint4(hi[0], hi[1], hi[2], hi[3]);
                *(uint4*)(smem + SME_ALO + r * SROW + k0 * 2) = make_uint4(lo[0], lo[1], lo[2], lo[3]);
            }
        }
        __syncthreads();

        // ---- MMA mainloop: fused hi-phase then lo-phase ----
        float acc[2][4][4];
#pragma unroll
        for (int mf = 0; mf < 2; mf++)
#pragma unroll
            for (int nf = 0; nf < 4; nf++)
#pragma unroll
                for (int q = 0; q < 4; q++) acc[mf][nf][q] = 0.f;

#pragma unroll
        for (int ks = 0; ks < 8; ks++) {
            uint32_t kb = ks * 32;
            uint32_t afrag[2][4];
            ldmx4(afrag[0], aBaseHi + kb);
            ldmx4(afrag[1], aBaseHi + 16 * SROW + kb);
            uint32_t bh[2][4], bl[2][4];
            ldmx4(bh[0], bBaseH + kb);
            ldmx4(bh[1], bBaseH + 16 * SROW + kb);
            ldmx4(bl[0], bBaseL + kb);
            ldmx4(bl[1], bBaseL + 16 * SROW + kb);
#pragma unroll
            for (int mf = 0; mf < 2; mf++)
#pragma unroll
                for (int nf = 0; nf < 4; nf++) {
                    mma16816(acc[mf][nf], afrag[mf],
                             bh[nf >> 1][(nf & 1) * 2], bh[nf >> 1][(nf & 1) * 2 + 1]);
                    mma16816(acc[mf][nf], afrag[mf],
                             bl[nf >> 1][(nf & 1) * 2], bl[nf >> 1][(nf & 1) * 2 + 1]);
                }
        }
#pragma unroll
        for (int ks = 0; ks < 8; ks++) {
            uint32_t kb = ks * 32;
            uint32_t afrag[2][4];
            ldmx4(afrag[0], aBaseLo + kb);
            ldmx4(afrag[1], aBaseLo + 16 * SROW + kb);
            uint32_t bh[2][4];
            ldmx4(bh[0], bBaseH + kb);
            ldmx4(bh[1], bBaseH + 16 * SROW + kb);
#pragma unroll
            for (int mf = 0; mf < 2; mf++)
#pragma unroll
                for (int nf = 0; nf < 4; nf++)
                    mma16816(acc[mf][nf], afrag[mf],
                             bh[nf >> 1][(nf & 1) * 2], bh[nf >> 1][(nf & 1) * 2 + 1]);
        }

        // ---- epilogue: store C + fused si/sj ----
        int qrow = lane >> 2;
        int qcol = (lane & 3) * 2;
        float pi[4] = {0.f, 0.f, 0.f, 0.f};
        float pj[4] = {0.f, 0.f, 0.f, 0.f};
#pragma unroll
        for (int mf = 0; mf < 2; mf++) {
#pragma unroll
            for (int half = 0; half < 2; half++) {
                int rloc = warpM * 32 + mf * 16 + half * 8 + qrow;
                int grow = block_row + rloc;
                float rpi = 0.f, rpj = 0.f;
#pragma unroll
                for (int nf = 0; nf < 4; nf++) {
                    int col = warpN * 32 + nf * 8 + qcol;
                    float c0 = acc[mf][nf][half * 2 + 0];
                    float c1 = acc[mf][nf][half * 2 + 1];
                    rpi = fmaf(c0, attS[col], rpi);
                    rpi = fmaf(c1, attS[col + 1], rpi);
                    rpj = fmaf(c0, attS[128 + col], rpj);
                    rpj = fmaf(c1, attS[128 + col + 1], rpj);
                    if (grow < Mrows)
                        *(float2*)(C + (size_t)grow * 128 + col) = make_float2(c0, c1);
                }
                pi[mf * 2 + half] = rpi;
                pj[mf * 2 + half] = rpj;
            }
        }
#pragma unroll
        for (int off = 1; off < 4; off <<= 1) {
#pragma unroll
            for (int q = 0; q < 4; q++) {
                pi[q] += __shfl_xor_sync(0xffffffffu, pi[q], off);
                pj[q] += __shfl_xor_sync(0xffffffffu, pj[q], off);
            }
        }
        if ((lane & 3) == 0) {
#pragma unroll
            for (int mf = 0; mf < 2; mf++)
#pragma unroll
                for (int half = 0; half < 2; half++) {
                    int rloc = warpM * 32 + mf * 16 + half * 8 + qrow;
                    redI[warpN * 64 + rloc] = pi[mf * 2 + half];
                    redJ[warpN * 64 + rloc] = pj[mf * 2 + half];
                }
        }
        __syncthreads();
        if (tid < TROWS) {
            int grow = block_row + tid;
            if (grow < Mrows) {
                g_si[grow] = (redI[tid] + redI[64 + tid]) + (redI[128 + tid] + redI[192 + tid]);
                g_sj[grow] = (redJ[tid] + redJ[64 + tid]) + (redJ[128 + tid] + redJ[192 + tid]);
                g_den[grow] = 0.f;
            }
        }
        __syncthreads();
    }
}

// ---------------- edge pass: 2 edges/thread, leaky + exp + den atomics ----------------
// block 0 also zeroes the BN accumulators (after GEMM L consumed them, before agg L)
__global__ void k_edge() {
    if (blockIdx.x == 0 && threadIdx.x < 128) {
        g_bnsum[threadIdx.x] = 0.f;
        g_bnsq[threadIdx.x] = 0.f;
    }
    int pos = (blockIdx.x * blockDim.x + threadIdx.x) * 2;
    if (pos >= ET) return;
    int2 ss = *(const int2*)(g_srcpos + pos);
    int2 dd = *(const int2*)(g_dstpos + pos);
    float a0 = g_si[dd.x] + g_sj[ss.x];
    float a1 = g_si[dd.y] + g_sj[ss.y];
    a0 = (a0 > 0.f) ? a0 : 0.2f * a0;   // NEG_GAT
    a1 = (a1 > 0.f) ? a1 : 0.2f * a1;
    float e0 = __expf(a0);
    float e1 = __expf(a1);
    *(float2*)(g_alpha + pos) = make_float2(e0, e1);
    atomicAdd(&g_den[ss.x], e0);
    atomicAdd(&g_den[ss.y], e1);
}

// ---------------- aggregation: warp-per-node (x AGG_NPW), 4-deep MLP ----------------
__global__ void __launch_bounds__(256)
k_aggregate(const float* __restrict__ h, const float* __restrict__ bias,
            float* __restrict__ out) {
    __shared__ float sB[8][128];
    __shared__ float sQ[8][128];
    int lane = threadIdx.x & 31;
    int w = threadIdx.x >> 5;    // warp in block 0..7
    int v0 = (blockIdx.x * 8 + w) * AGG_NPW;
    int c4 = lane * 4;
    float4 bi = *(const float4*)(bias + c4);
    float4 bsum = make_float4(0.f, 0.f, 0.f, 0.f);
    float4 bsq  = make_float4(0.f, 0.f, 0.f, 0.f);
#pragma unroll
    for (int n = 0; n < AGG_NPW; n++) {
        int v = v0 + n;
        if (v >= Nn) break;
        int s = g_off[v];
        int e = g_off[v + 1];
        float4 a0 = make_float4(0.f, 0.f, 0.f, 0.f);
        float4 a1 = make_float4(0.f, 0.f, 0.f, 0.f);
        float4 a2 = make_float4(0.f, 0.f, 0.f, 0.f);
        float4 a3 = make_float4(0.f, 0.f, 0.f, 0.f);
        int i = s;
        for (; i + 3 < e; i += 4) {
            int s0 = g_srcpos[i];
            int s1 = g_srcpos[i + 1];
            int s2 = g_srcpos[i + 2];
            int s3 = g_srcpos[i + 3];
            float w0 = __fdividef(g_alpha[i],     g_den[s0] + 1e-16f);
            float w1 = __fdividef(g_alpha[i + 1], g_den[s1] + 1e-16f);
            float w2 = __fdividef(g_alpha[i + 2], g_den[s2] + 1e-16f);
            float w3 = __fdividef(g_alpha[i + 3], g_den[s3] + 1e-16f);
            float4 h0 = *(const float4*)(h + (size_t)s0 * 128 + c4);
            float4 h1 = *(const float4*)(h + (size_t)s1 * 128 + c4);
            float4 h2 = *(const float4*)(h + (size_t)s2 * 128 + c4);
            float4 h3 = *(const float4*)(h + (size_t)s3 * 128 + c4);
            a0.x = fmaf(w0, h0.x, a0.x); a0.y = fmaf(w0, h0.y, a0.y);
            a0.z = fmaf(w0, h0.z, a0.z); a0.w = fmaf(w0, h0.w, a0.w);
            a1.x = fmaf(w1, h1.x, a1.x); a1.y = fmaf(w1, h1.y, a1.y);
            a1.z = fmaf(w1, h1.z, a1.z); a1.w = fmaf(w1, h1.w, a1.w);
            a2.x = fmaf(w2, h2.x, a2.x); a2.y = fmaf(w2, h2.y, a2.y);
            a2.z = fmaf(w2, h2.z, a2.z); a2.w = fmaf(w2, h2.w, a2.w);
            a3.x = fmaf(w3, h3.x, a3.x); a3.y = fmaf(w3, h3.y, a3.y);
            a3.z = fmaf(w3, h3.z, a3.z); a3.w = fmaf(w3, h3.w, a3.w);
        }
        for (; i < e; i++) {
            int s0 = g_srcpos[i];
            float w0 = __fdividef(g_alpha[i], g_den[s0] + 1e-16f);
            float4 h0 = *(const float4*)(h + (size_t)s0 * 128 + c4);
            a0.x = fmaf(w0, h0.x, a0.x); a0.y = fmaf(w0, h0.y, a0.y);
            a0.z = fmaf(w0, h0.z, a0.z); a0.w = fmaf(w0, h0.w, a0.w);
        }
        float4 u;
        u.x = (a0.x + a1.x) + (a2.x + a3.x) + bi.x;
        u.y = (a0.y + a1.y) + (a2.y + a3.y) + bi.y;
        u.z = (a0.z + a1.z) + (a2.z + a3.z) + bi.z;
        u.w = (a0.w + a1.w) + (a2.w + a3.w) + bi.w;
        u.x = (u.x > 0.f) ? u.x : 0.f;
        u.y = (u.y > 0.f) ? u.y : 0.f;
        u.z = (u.z > 0.f) ? u.z : 0.f;
        u.w = (u.w > 0.f) ? u.w : 0.f;
        *(float4*)(out + (size_t)v * 128 + c4) = u;
        bsum.x += u.x; bsum.y += u.y; bsum.z += u.z; bsum.w += u.w;
        bsq.x = fmaf(u.x, u.x, bsq.x); bsq.y = fmaf(u.y, u.y, bsq.y);
        bsq.z = fmaf(u.z, u.z, bsq.z); bsq.w = fmaf(u.w, u.w, bsq.w);
    }
    *(float4*)&sB[w][c4] = bsum;
    *(float4*)&sQ[w][c4] = bsq;
    __syncthreads();
    int c = threadIdx.x;
    if (c < 128) {
        float ssum = 0.f, ssq = 0.f;
#pragma unroll
        for (int ww = 0; ww < 8; ww++) {
            ssum += sB[ww][c];
            ssq  += sQ[ww][c];
        }
        atomicAdd(&g_bnsum[c], ssum);
        atomicAdd(&g_bnsq[c], ssq);
    }
}

// ---------------- decoder: M = P1 @ P2 @ P1^T ----------------
__global__ void k_m2(const float* __restrict__ P1, const float* __restrict__ P2) {
    __shared__ float p1r[64];
    __shared__ float qrow[64];
    int r = blockIdx.x;
    int t = threadIdx.x;
    if (t < 64) p1r[t] = P1[r * 64 + t];
    __syncthreads();
    if (t < 64) {
        float a0 = 0.f, a1 = 0.f, a2 = 0.f, a3 = 0.f;
#pragma unroll
        for (int k = 0; k < 64; k += 4) {
            a0 = fmaf(p1r[k + 0], P2[(k + 0) * 64 + t], a0);
            a1 = fmaf(p1r[k + 1], P2[(k + 1) * 64 + t], a1);
            a2 = fmaf(p1r[k + 2], P2[(k + 2) * 64 + t], a2);
            a3 = fmaf(p1r[k + 3], P2[(k + 3) * 64 + t], a3);
        }
        qrow[t] = (a0 + a1) + (a2 + a3);
    }
    __syncthreads();
    float a0 = 0.f, a1 = 0.f, a2 = 0.f, a3 = 0.f;
#pragma unroll
    for (int k = 0; k < 64; k += 4) {
        a0 = fmaf(qrow[k + 0], P1[t * 64 + k + 0], a0);
        a1 = fmaf(qrow[k + 1], P1[t * 64 + k + 1], a1);
        a2 = fmaf(qrow[k + 2], P1[t * 64 + k + 2], a2);
        a3 = fmaf(qrow[k + 3], P1[t * 64 + k + 3], a3);
    }
    g_M[r * 128 + t] = (a0 + a1) + (a2 + a3);
}

// ---------------- decoder: ypred = a^T M b (BN+leaky inline) ----------------
__global__ void k_decode(const float* __restrict__ h, const int* __restrict__ drug,
                         const float* __restrict__ gamma, const float* __restrict__ beta,
                         float* __restrict__ out) {
    __shared__ float ash[128];
    __shared__ float bsh[128];
    __shared__ float wsum[4];
    int b = blockIdx.x;
    int t = threadIdx.x;
    int ia = drug[b * 2 + 0] - 1;
    int ib = drug[b * 2 + 1] - 1;
    const float invN = 1.f / (float)Nn;
    float mu = g_bnsum[t] * invN;
    float var = g_bnsq[t] * invN - mu * mu;
    float sc = rsqrtf(var + BN_EPS) * gamma[t];
    float sh = beta[t] - mu * sc;
    float ya = h[(size_t)ia * 128 + t] * sc + sh;
    float yb = h[(size_t)ib * 128 + t] * sc + sh;
    ash[t] = (ya > 0.f) ? ya : 0.1f * ya;
    bsh[t] = (yb > 0.f) ? yb : 0.1f * yb;
    __syncthreads();
    float acc = 0.f;
#pragma unroll 8
    for (int d = 0; d < 128; d++) acc = fmaf(ash[d], g_M[d * 128 + t], acc);
    float val = acc * bsh[t];
#pragma unroll
    for (int o = 16; o > 0; o >>= 1) val += __shfl_down_sync(0xffffffffu, val, o);
    if ((t & 31) == 0) wsum[t >> 5] = val;
    __syncthreads();
    if (t == 0) out[b] = wsum[0] + wsum[1] + wsum[2] + wsum[3];
}

// ---------------- launch ----------------
extern "C" void kernel_launch(void* const* d_in, const int* in_sizes, int n_in,
                              void* d_out, int out_size) {
    const float* x    = (const float*)d_in[0];
    const int*   ei   = (const int*)d_in[1];
    const int*   drug = (const int*)d_in[2];
    const float* Wl[3]  = { (const float*)d_in[3],  (const float*)d_in[8],  (const float*)d_in[13] };
    const float* attl[3]= { (const float*)d_in[4],  (const float*)d_in[9],  (const float*)d_in[14] };
    const float* bl[3]  = { (const float*)d_in[5],  (const float*)d_in[10], (const float*)d_in[15] };
    const float* gl[3]  = { (const float*)d_in[6],  (const float*)d_in[11], (const float*)d_in[16] };
    const float* bel[3] = { (const float*)d_in[7],  (const float*)d_in[12], (const float*)d_in[17] };
    const float* P1 = (const float*)d_in[18];
    const float* P2 = (const float*)d_in[19];
    float* out = (float*)d_out;

    void* pA_; void* pB_; void* pDeg_; void* pWhi_; void* pWlo_;
    cudaGetSymbolAddress(&pA_, g_bufA);
    cudaGetSymbolAddress(&pB_, g_bufB);
    cudaGetSymbolAddress(&pDeg_, g_deg);
    cudaGetSymbolAddress(&pWhi_, g_WhiAll);
    cudaGetSymbolAddress(&pWlo_, g_WloAll);
    float* bufA = (float*)pA_;
    float* bufB = (float*)pB_;
    const uint4* whiAll = (const uint4*)pWhi_;
    const uint4* wloAll = (const uint4*)pWlo_;

    static cudaStream_t s1 = nullptr;
    static cudaEvent_t evFork = nullptr, evG0 = nullptr, evM2 = nullptr;
    if (!s1) {
        cudaStreamCreateWithFlags(&s1, cudaStreamNonBlocking);
        cudaEventCreateWithFlags(&evFork, cudaEventDisableTiming);
        cudaEventCreateWithFlags(&evG0, cudaEventDisableTiming);
        cudaEventCreateWithFlags(&evM2, cudaEventDisableTiming);
        cudaFuncSetAttribute(k_gemm_mma<false>, cudaFuncAttributeMaxDynamicSharedMemorySize, SME_TOTAL);
        cudaFuncSetAttribute(k_gemm_mma<true>,  cudaFuncAttributeMaxDynamicSharedMemorySize, SME_TOTAL);
    }

    const int EB = 256;
    const int egrid = (ET + EB - 1) / EB;
    const int e2grid = (ET / 2 + EB - 1) / EB;                   // 2 edges/thread
    const int agg_grid = (Nn + 8 * AGG_NPW - 1) / (8 * AGG_NPW); // 1563

    // ---- fork: side stream does W prep + GEMM L0 + decoder M while main builds CSR ----
    cudaMemsetAsync(pDeg_, 0, Nn * sizeof(int), 0);
    cudaEventRecord(evFork, 0);
    cudaStreamWaitEvent(s1, evFork, 0);

    // side stream
    k_wsplit_all<<<24, 256, 0, s1>>>(Wl[0], Wl[1], Wl[2]);
    k_gemm_mma<false><<<GEMM_GRID, 256, SME_TOTAL, s1>>>(
        x, attl[0], nullptr, nullptr, whiAll, wloAll, bufA, Nn);
    cudaEventRecord(evG0, s1);
    k_m2<<<128, 128, 0, s1>>>(P1, P2);
    cudaEventRecord(evM2, s1);

    // main stream: CSR build (by dst)
    k_count<<<egrid, EB>>>(ei);
    k_scan<<<1, 1024>>>();
    k_scatter<<<egrid, EB>>>(ei);

    // join: edge L0 needs GEMM L0's si/sj/den
    cudaStreamWaitEvent(0, evG0, 0);

    const float* layer_in = bufB;
    for (int L = 0; L < 3; L++) {
        if (L > 0) {
            k_gemm_mma<true><<<GEMM_GRID, 256, SME_TOTAL>>>(
                layer_in, attl[L], gl[L - 1], bel[L - 1],
                whiAll + L * 2048, wloAll + L * 2048, bufA, Nn);
        }
        k_edge<<<e2grid, EB>>>();
        k_aggregate<<<agg_grid, 256>>>(bufA, bl[L], bufB);
        layer_in = bufB;
    }

    cudaStreamWaitEvent(0, evM2, 0);
    k_decode<<<Bb, 128>>>(bufB, drug, gl[2], bel[2], out);
}

// round 16
// speedup vs baseline: 1.2127x; 1.2127x over previous
#include <cuda_runtime.h>
#include <cuda_bf16.h>
#include <float.h>
#include <math.h>
#include <stdint.h>

// Problem constants (fixed by the reference)
#define Nn 50000
#define Ee 600000
#define ET (Ee + Nn)     // edges + self loops = 650000 (even; Ee even)
#define D  128
#define Bb 1024
#define BN_EPS 1e-5f
#define AGG_NPW 4        // nodes per warp in aggregation
#define TROWS 64         // GEMM tile rows
#define NTILES ((Nn + TROWS - 1) / TROWS)   // 782
#define GEMM_GRID (NTILES / 2)              // 391, 2 tiles per CTA

// ---------------- static device scratch ----------------
__device__ float g_bufA[Nn * D];      // GEMM output h (fp32)
__device__ float g_bufB[Nn * D];      // aggregated output
__device__ float g_si[Nn], g_sj[Nn];
__device__ float g_den[Nn];           // sum of exp per src node (raw)
__device__ float g_alpha[ET];         // exp(alpha), CSR-position order
__device__ int   g_srcpos[ET];
__device__ int   g_dstpos[ET];
__device__ int   g_deg[Nn];
__device__ int   g_off[Nn + 1];
__device__ int   g_cur[Nn];
__device__ float g_bnsum[D], g_bnsq[D];
__device__ float g_M[D * D];
// padded-row bf16 split images of W for all 3 layers: [3][2048] uint4 each
__device__ uint4 g_WhiAll[3 * 2048];
__device__ uint4 g_WloAll[3 * 2048];

// ---------------- PTX helpers (plain compute_103-safe) ----------------
__device__ __forceinline__ uint32_t smem_u32(const void* p) {
    uint32_t a;
    asm("{ .reg .u64 t; cvta.to.shared.u64 t, %1; cvt.u32.u64 %0, t; }" : "=r"(a) : "l"(p));
    return a;
}

__device__ __forceinline__ void ldmx4(uint32_t* r, uint32_t addr) {
    asm volatile("ldmatrix.sync.aligned.m8n8.x4.shared.b16 {%0,%1,%2,%3}, [%4];"
                 : "=r"(r[0]), "=r"(r[1]), "=r"(r[2]), "=r"(r[3]) : "r"(addr));
}

__device__ __forceinline__ void mma16816(float* c, const uint32_t* a, uint32_t b0, uint32_t b1) {
    asm volatile(
        "mma.sync.aligned.m16n8k16.row.col.f32.bf16.bf16.f32 "
        "{%0,%1,%2,%3}, {%4,%5,%6,%7}, {%8,%9}, {%0,%1,%2,%3};"
        : "+f"(c[0]), "+f"(c[1]), "+f"(c[2]), "+f"(c[3])
        : "r"(a[0]), "r"(a[1]), "r"(a[2]), "r"(a[3]), "r"(b0), "r"(b1));
}

// ---------------- CSR build (by dst), 2 edges/thread ----------------
__global__ void k_count(const int* __restrict__ ei) {
    int pos = (blockIdx.x * blockDim.x + threadIdx.x) * 2;
    if (pos >= ET) return;
    int d0, d1;
    if (pos < Ee) {
        int2 dd = *(const int2*)(ei + Ee + pos);
        d0 = dd.x; d1 = dd.y;
    } else {
        d0 = pos - Ee; d1 = pos + 1 - Ee;
    }
    atomicAdd(&g_deg[d0], 1);
    atomicAdd(&g_deg[d1], 1);
}

__global__ void k_scan() {
    __shared__ int part[1024];
    int tid = threadIdx.x;
    const int CH = (Nn + 1023) / 1024;
    int base = tid * CH;
    int s = 0;
    for (int i = 0; i < CH; i++) {
        int idx = base + i;
        if (idx < Nn) s += g_deg[idx];
    }
    part[tid] = s;
    __syncthreads();
    for (int d = 1; d < 1024; d <<= 1) {
        int v = (tid >= d) ? part[tid - d] : 0;
        __syncthreads();
        part[tid] += v;
        __syncthreads();
    }
    int run = (tid > 0) ? part[tid - 1] : 0;
    for (int i = 0; i < CH; i++) {
        int idx = base + i;
        if (idx < Nn) {
            g_off[idx] = run;
            g_cur[idx] = run;
            run += g_deg[idx];
        }
    }
    if (tid == 1023) g_off[Nn] = part[1023];
}

__global__ void k_scatter(const int* __restrict__ ei) {
    int pos = (blockIdx.x * blockDim.x + threadIdx.x) * 2;
    if (pos >= ET) return;
    int s0, s1, d0, d1;
    if (pos < Ee) {
        int2 ss = *(const int2*)(ei + pos);
        int2 dd = *(const int2*)(ei + Ee + pos);
        s0 = ss.x; s1 = ss.y; d0 = dd.x; d1 = dd.y;
    } else {
        s0 = pos - Ee; s1 = pos + 1 - Ee;
        d0 = s0; d1 = s1;
    }
    int p0 = atomicAdd(&g_cur[d0], 1);
    g_srcpos[p0] = s0;
    g_dstpos[p0] = d0;
    int p1 = atomicAdd(&g_cur[d1], 1);
    g_srcpos[p1] = s1;
    g_dstpos[p1] = d1;
}

#define SROW 272

// ---------------- W split: fp32 -> padded-row bf16 hi/lo images (one layer) ----------
__global__ void k_wsplit(const float* __restrict__ W, int L) {
    int idx = blockIdx.x * blockDim.x + threadIdx.x;  // 0..2047
    if (idx >= 2048) return;
    int n = idx >> 4;           // row (out channel)
    int k0 = (idx & 15) * 8;    // 8 consecutive k
    const float* src = W + n * 128 + k0;
    float v[8];
#pragma unroll
    for (int j = 0; j < 8; j++) v[j] = src[j];
    uint32_t hi[4], lo[4];
#pragma unroll
    for (int j = 0; j < 4; j++) {
        __nv_bfloat162 hp = __floats2bfloat162_rn(v[2 * j], v[2 * j + 1]);
        float2 hf = __bfloat1622float2(hp);
        __nv_bfloat162 lp = __floats2bfloat162_rn(v[2 * j] - hf.x, v[2 * j + 1] - hf.y);
        hi[j] = *reinterpret_cast<uint32_t*>(&hp);
        lo[j] = *reinterpret_cast<uint32_t*>(&lp);
    }
    g_WhiAll[L * 2048 + idx] = make_uint4(hi[0], hi[1], hi[2], hi[3]);
    g_WloAll[L * 2048 + idx] = make_uint4(lo[0], lo[1], lo[2], lo[3]);
}

// ---------------- HMMA GEMM: C = A' @ W^T, 2 tiles per CTA, 2 CTAs/SM ----------------
#define SME_ATT  0
#define SME_SC   1024
#define SME_SH   1536
#define SME_REDI 2048
#define SME_REDJ 3072
#define SME_AHI  4096
#define SME_ALO  (SME_AHI + TROWS * SROW)
#define SME_WHI  (SME_ALO + TROWS * SROW)
#define SME_WLO  (SME_WHI + 128 * SROW)
#define SME_TOTAL (SME_WLO + 128 * SROW)   // 108544 B -> 2 CTAs/SM

template <bool BN>
__global__ void __launch_bounds__(256, 2)
k_gemm_mma(const float* __restrict__ A, const float* __restrict__ att,
           const float* __restrict__ gamma, const float* __restrict__ beta,
           const uint4* __restrict__ whiG, const uint4* __restrict__ wloG,
           float* __restrict__ C, int Mrows) {
    extern __shared__ char smem[];
    uint32_t sb = smem_u32(smem);
    int tid = threadIdx.x;
    int wid = tid >> 5;
    int lane = tid & 31;
    int warpM = wid & 1;   // 0..1, 32 rows each
    int warpN = wid >> 1;  // 0..3, 32 cols each

    float* attS = (float*)(smem + SME_ATT);
    float* scS  = (float*)(smem + SME_SC);
    float* shS  = (float*)(smem + SME_SH);
    float* redI = (float*)(smem + SME_REDI);
    float* redJ = (float*)(smem + SME_REDJ);

    if (tid < 256) attS[tid] = att[tid];
    if (BN && tid < 128) {
        const float invN = 1.f / (float)Nn;
        float mu = g_bnsum[tid] * invN;
        float var = g_bnsq[tid] * invN - mu * mu;
        float sc = rsqrtf(var + BN_EPS) * gamma[tid];
        scS[tid] = sc;
        shS[tid] = beta[tid] - mu * sc;
    }

    // copy padded W images into smem (once per CTA, reused across tiles)
    for (int i = tid; i < 2048; i += 256) {
        int r = i >> 4;
        int c = i & 15;
        *(uint4*)(smem + SME_WHI + r * SROW + c * 16) = whiG[i];
        *(uint4*)(smem + SME_WLO + r * SROW + c * 16) = wloG[i];
    }
    __syncthreads();   // W + BN coefficients ready

    // lane-invariant addressing
    int a_row = lane & 15;
    int a_k   = (lane >> 4) * 8;
    uint32_t aLaneOff = a_row * SROW + a_k * 2;
    int b_n = (lane & 7) + ((lane >> 4) << 3);
    int b_k = ((lane >> 3) & 1) * 8;
    uint32_t bLaneOff = b_n * SROW + b_k * 2;
    uint32_t aBaseHi = sb + SME_AHI + (warpM * 32) * SROW + aLaneOff;
    uint32_t aBaseLo = sb + SME_ALO + (warpM * 32) * SROW + aLaneOff;
    uint32_t bBaseH  = sb + SME_WHI + (warpN * 32) * SROW + bLaneOff;
    uint32_t bBaseL  = sb + SME_WLO + (warpN * 32) * SROW + bLaneOff;

    for (int tile = blockIdx.x; tile < NTILES; tile += gridDim.x) {
        int block_row = tile * TROWS;

        // convert A tile (64 rows) -> bf16 hi/lo (padded rows)
        {
            int r = tid >> 2;               // 0..63
            int kq = (tid & 3) * 32;        // quarter-row
            int grow = block_row + r;
            bool valid = (grow < Mrows);
            const float* arow = A + (size_t)grow * 128 + kq;
#pragma unroll
            for (int c = 0; c < 4; c++) {   // 4 chunks of 8 floats
                int k0 = kq + c * 8;
                float v[8];
                if (valid) {
                    float4 p0 = *(const float4*)(arow + c * 8);
                    float4 p1 = *(const float4*)(arow + c * 8 + 4);
                    v[0] = p0.x; v[1] = p0.y; v[2] = p0.z; v[3] = p0.w;
                    v[4] = p1.x; v[5] = p1.y; v[6] = p1.z; v[7] = p1.w;
                } else {
#pragma unroll
                    for (int j = 0; j < 8; j++) v[j] = 0.f;
                }
                if (BN) {
#pragma unroll
                    for (int j = 0; j < 8; j++) {
                        float y = v[j] * scS[k0 + j] + shS[k0 + j];
                        v[j] = (y > 0.f) ? y : 0.1f * y;
                    }
                }
                uint32_t hi[4], lo[4];
#pragma unroll
                for (int j = 0; j < 4; j++) {
                    __nv_bfloat162 hp = __floats2bfloat162_rn(v[2 * j], v[2 * j + 1]);
                    float2 hf = __bfloat1622float2(hp);
                    __nv_bfloat162 lp = __floats2bfloat162_rn(v[2 * j] - hf.x, v[2 * j + 1] - hf.y);
                    hi[j] = *reinterpret_cast<uint32_t*>(&hp);
                    lo[j] = *reinterpret_cast<uint32_t*>(&lp);
                }
                *(uint4*)(smem + SME_AHI + r * SROW + k0 * 2) = make_uint4(hi[0], hi[1], hi[2], hi[3]);
                *(uint4*)(smem + SME_ALO + r * SROW + k0 * 2) = make_uint4(lo[0], lo[1], lo[2], lo[3]);
            }
        }
        __syncthreads();

        // ---- MMA mainloop: fused hi-phase then lo-phase ----
        float acc[2][4][4];
#pragma unroll
        for (int mf = 0; mf < 2; mf++)
#pragma unroll
            for (int nf = 0; nf < 4; nf++)
#pragma unroll
                for (int q = 0; q < 4; q++) acc[mf][nf][q] = 0.f;

#pragma unroll
        for (int ks = 0; ks < 8; ks++) {
            uint32_t kb = ks * 32;
            uint32_t afrag[2][4];
            ldmx4(afrag[0], aBaseHi + kb);
            ldmx4(afrag[1], aBaseHi + 16 * SROW + kb);
            uint32_t bh[2][4], bl[2][4];
            ldmx4(bh[0], bBaseH + kb);
            ldmx4(bh[1], bBaseH + 16 * SROW + kb);
            ldmx4(bl[0], bBaseL + kb);
            ldmx4(bl[1], bBaseL + 16 * SROW + kb);
#pragma unroll
            for (int mf = 0; mf < 2; mf++)
#pragma unroll
                for (int nf = 0; nf < 4; nf++) {
                    mma16816(acc[mf][nf], afrag[mf],
                             bh[nf >> 1][(nf & 1) * 2], bh[nf >> 1][(nf & 1) * 2 + 1]);
                    mma16816(acc[mf][nf], afrag[mf],
                             bl[nf >> 1][(nf & 1) * 2], bl[nf >> 1][(nf & 1) * 2 + 1]);
                }
        }
#pragma unroll
        for (int ks = 0; ks < 8; ks++) {
            uint32_t kb = ks * 32;
            uint32_t afrag[2][4];
            ldmx4(afrag[0], aBaseLo + kb);
            ldmx4(afrag[1], aBaseLo + 16 * SROW + kb);
            uint32_t bh[2][4];
            ldmx4(bh[0], bBaseH + kb);
            ldmx4(bh[1], bBaseH + 16 * SROW + kb);
#pragma unroll
            for (int mf = 0; mf < 2; mf++)
#pragma unroll
                for (int nf = 0; nf < 4; nf++)
                    mma16816(acc[mf][nf], afrag[mf],
                             bh[nf >> 1][(nf & 1) * 2], bh[nf >> 1][(nf & 1) * 2 + 1]);
        }

        // ---- epilogue: store C + fused si/sj ----
        int qrow = lane >> 2;
        int qcol = (lane & 3) * 2;
        float pi[4] = {0.f, 0.f, 0.f, 0.f};
        float pj[4] = {0.f, 0.f, 0.f, 0.f};
#pragma unroll
        for (int mf = 0; mf < 2; mf++) {
#pragma unroll
            for (int half = 0; half < 2; half++) {
                int rloc = warpM * 32 + mf * 16 + half * 8 + qrow;
                int grow = block_row + rloc;
                float rpi = 0.f, rpj = 0.f;
#pragma unroll
                for (int nf = 0; nf < 4; nf++) {
                    int col = warpN * 32 + nf * 8 + qcol;
                    float c0 = acc[mf][nf][half * 2 + 0];
                    float c1 = acc[mf][nf][half * 2 + 1];
                    rpi = fmaf(c0, attS[col], rpi);
                    rpi = fmaf(c1, attS[col + 1], rpi);
                    rpj = fmaf(c0, attS[128 + col], rpj);
                    rpj = fmaf(c1, attS[128 + col + 1], rpj);
                    if (grow < Mrows)
                        *(float2*)(C + (size_t)grow * 128 + col) = make_float2(c0, c1);
                }
                pi[mf * 2 + half] = rpi;
                pj[mf * 2 + half] = rpj;
            }
        }
#pragma unroll
        for (int off = 1; off < 4; off <<= 1) {
#pragma unroll
            for (int q = 0; q < 4; q++) {
                pi[q] += __shfl_xor_sync(0xffffffffu, pi[q], off);
                pj[q] += __shfl_xor_sync(0xffffffffu, pj[q], off);
            }
        }
        if ((lane & 3) == 0) {
#pragma unroll
            for (int mf = 0; mf < 2; mf++)
#pragma unroll
                for (int half = 0; half < 2; half++) {
                    int rloc = warpM * 32 + mf * 16 + half * 8 + qrow;
                    redI[warpN * 64 + rloc] = pi[mf * 2 + half];
                    redJ[warpN * 64 + rloc] = pj[mf * 2 + half];
                }
        }
        __syncthreads();
        if (tid < TROWS) {
            int grow = block_row + tid;
            if (grow < Mrows) {
                g_si[grow] = (redI[tid] + redI[64 + tid]) + (redI[128 + tid] + redI[192 + tid]);
                g_sj[grow] = (redJ[tid] + redJ[64 + tid]) + (redJ[128 + tid] + redJ[192 + tid]);
                g_den[grow] = 0.f;
            }
        }
        __syncthreads();
    }
}

// ---------------- edge pass: 2 edges/thread, leaky + exp + den atomics ----------------
// block 0 also zeroes the BN accumulators (after GEMM L consumed them, before agg L)
__global__ void k_edge() {
    if (blockIdx.x == 0 && threadIdx.x < 128) {
        g_bnsum[threadIdx.x] = 0.f;
        g_bnsq[threadIdx.x] = 0.f;
    }
    int pos = (blockIdx.x * blockDim.x + threadIdx.x) * 2;
    if (pos >= ET) return;
    int2 ss = *(const int2*)(g_srcpos + pos);
    int2 dd = *(const int2*)(g_dstpos + pos);
    float a0 = g_si[dd.x] + g_sj[ss.x];
    float a1 = g_si[dd.y] + g_sj[ss.y];
    a0 = (a0 > 0.f) ? a0 : 0.2f * a0;   // NEG_GAT
    a1 = (a1 > 0.f) ? a1 : 0.2f * a1;
    float e0 = __expf(a0);
    float e1 = __expf(a1);
    *(float2*)(g_alpha + pos) = make_float2(e0, e1);
    atomicAdd(&g_den[ss.x], e0);
    atomicAdd(&g_den[ss.y], e1);
}

// ---------------- aggregation: warp-per-node (x AGG_NPW), float4 lanes (R14 form) ----
__global__ void __launch_bounds__(256)
k_aggregate(const float* __restrict__ h, const float* __restrict__ bias,
            float* __restrict__ out) {
    __shared__ float sB[8][128];
    __shared__ float sQ[8][128];
    int lane = threadIdx.x & 31;
    int w = threadIdx.x >> 5;    // warp in block 0..7
    int v0 = (blockIdx.x * 8 + w) * AGG_NPW;
    int c4 = lane * 4;
    float4 bi = *(const float4*)(bias + c4);
    float4 bsum = make_float4(0.f, 0.f, 0.f, 0.f);
    float4 bsq  = make_float4(0.f, 0.f, 0.f, 0.f);
#pragma unroll
    for (int n = 0; n < AGG_NPW; n++) {
        int v = v0 + n;
        if (v >= Nn) break;
        int s = g_off[v];
        int e = g_off[v + 1];
        float4 a0 = make_float4(0.f, 0.f, 0.f, 0.f);
        float4 a1 = make_float4(0.f, 0.f, 0.f, 0.f);
        int i = s;
        for (; i + 1 < e; i += 2) {
            int s0 = g_srcpos[i];
            int s1 = g_srcpos[i + 1];
            float w0 = __fdividef(g_alpha[i], g_den[s0] + 1e-16f);
            float w1 = __fdividef(g_alpha[i + 1], g_den[s1] + 1e-16f);
            float4 h0 = *(const float4*)(h + (size_t)s0 * 128 + c4);
            float4 h1 = *(const float4*)(h + (size_t)s1 * 128 + c4);
            a0.x = fmaf(w0, h0.x, a0.x); a0.y = fmaf(w0, h0.y, a0.y);
            a0.z = fmaf(w0, h0.z, a0.z); a0.w = fmaf(w0, h0.w, a0.w);
            a1.x = fmaf(w1, h1.x, a1.x); a1.y = fmaf(w1, h1.y, a1.y);
            a1.z = fmaf(w1, h1.z, a1.z); a1.w = fmaf(w1, h1.w, a1.w);
        }
        if (i < e) {
            int s0 = g_srcpos[i];
            float w0 = __fdividef(g_alpha[i], g_den[s0] + 1e-16f);
            float4 h0 = *(const float4*)(h + (size_t)s0 * 128 + c4);
            a0.x = fmaf(w0, h0.x, a0.x); a0.y = fmaf(w0, h0.y, a0.y);
            a0.z = fmaf(w0, h0.z, a0.z); a0.w = fmaf(w0, h0.w, a0.w);
        }
        float4 u;
        u.x = a0.x + a1.x + bi.x; u.y = a0.y + a1.y + bi.y;
        u.z = a0.z + a1.z + bi.z; u.w = a0.w + a1.w + bi.w;
        u.x = (u.x > 0.f) ? u.x : 0.f;
        u.y = (u.y > 0.f) ? u.y : 0.f;
        u.z = (u.z > 0.f) ? u.z : 0.f;
        u.w = (u.w > 0.f) ? u.w : 0.f;
        *(float4*)(out + (size_t)v * 128 + c4) = u;
        bsum.x += u.x; bsum.y += u.y; bsum.z += u.z; bsum.w += u.w;
        bsq.x = fmaf(u.x, u.x, bsq.x); bsq.y = fmaf(u.y, u.y, bsq.y);
        bsq.z = fmaf(u.z, u.z, bsq.z); bsq.w = fmaf(u.w, u.w, bsq.w);
    }
    *(float4*)&sB[w][c4] = bsum;
    *(float4*)&sQ[w][c4] = bsq;
    __syncthreads();
    int c = threadIdx.x;
    if (c < 128) {
        float ssum = 0.f, ssq = 0.f;
#pragma unroll
        for (int ww = 0; ww < 8; ww++) {
            ssum += sB[ww][c];
            ssq  += sQ[ww][c];
        }
        atomicAdd(&g_bnsum[c], ssum);
        atomicAdd(&g_bnsq[c], ssq);
    }
}

// ---------------- decoder: M = P1 @ P2 @ P1^T ----------------
__global__ void k_m2(const float* __restrict__ P1, const float* __restrict__ P2) {
    __shared__ float p1r[64];
    __shared__ float qrow[64];
    int r = blockIdx.x;
    int t = threadIdx.x;
    if (t < 64) p1r[t] = P1[r * 64 + t];
    __syncthreads();
    if (t < 64) {
        float a0 = 0.f, a1 = 0.f, a2 = 0.f, a3 = 0.f;
#pragma unroll
        for (int k = 0; k < 64; k += 4) {
            a0 = fmaf(p1r[k + 0], P2[(k + 0) * 64 + t], a0);
            a1 = fmaf(p1r[k + 1], P2[(k + 1) * 64 + t], a1);
            a2 = fmaf(p1r[k + 2], P2[(k + 2) * 64 + t], a2);
            a3 = fmaf(p1r[k + 3], P2[(k + 3) * 64 + t], a3);
        }
        qrow[t] = (a0 + a1) + (a2 + a3);
    }
    __syncthreads();
    float a0 = 0.f, a1 = 0.f, a2 = 0.f, a3 = 0.f;
#pragma unroll
    for (int k = 0; k < 64; k += 4) {
        a0 = fmaf(qrow[k + 0], P1[t * 64 + k + 0], a0);
        a1 = fmaf(qrow[k + 1], P1[t * 64 + k + 1], a1);
        a2 = fmaf(qrow[k + 2], P1[t * 64 + k + 2], a2);
        a3 = fmaf(qrow[k + 3], P1[t * 64 + k + 3], a3);
    }
    g_M[r * 128 + t] = (a0 + a1) + (a2 + a3);
}

// ---------------- decoder: ypred = a^T M b (BN+leaky inline) ----------------
__global__ void k_decode(const float* __restrict__ h, const int* __restrict__ drug,
                         const float* __restrict__ gamma, const float* __restrict__ beta,
                         float* __restrict__ out) {
    __shared__ float ash[128];
    __shared__ float bsh[128];
    __shared__ float wsum[4];
    int b = blockIdx.x;
    int t = threadIdx.x;
    int ia = drug[b * 2 + 0] - 1;
    int ib = drug[b * 2 + 1] - 1;
    const float invN = 1.f / (float)Nn;
    float mu = g_bnsum[t] * invN;
    float var = g_bnsq[t] * invN - mu * mu;
    float sc = rsqrtf(var + BN_EPS) * gamma[t];
    float sh = beta[t] - mu * sc;
    float ya = h[(size_t)ia * 128 + t] * sc + sh;
    float yb = h[(size_t)ib * 128 + t] * sc + sh;
    ash[t] = (ya > 0.f) ? ya : 0.1f * ya;
    bsh[t] = (yb > 0.f) ? yb : 0.1f * yb;
    __syncthreads();
    float acc = 0.f;
#pragma unroll 8
    for (int d = 0; d < 128; d++) acc = fmaf(ash[d], g_M[d * 128 + t], acc);
    float val = acc * bsh[t];
#pragma unroll
    for (int o = 16; o > 0; o >>= 1) val += __shfl_down_sync(0xffffffffu, val, o);
    if ((t & 31) == 0) wsum[t >> 5] = val;
    __syncthreads();
    if (t == 0) out[b] = wsum[0] + wsum[1] + wsum[2] + wsum[3];
}

// ---------------- launch ----------------
extern "C" void kernel_launch(void* const* d_in, const int* in_sizes, int n_in,
                              void* d_out, int out_size) {
    const float* x    = (const float*)d_in[0];
    const int*   ei   = (const int*)d_in[1];
    const int*   drug = (const int*)d_in[2];
    const float* Wl[3]  = { (const float*)d_in[3],  (const float*)d_in[8],  (const float*)d_in[13] };
    const float* attl[3]= { (const float*)d_in[4],  (const float*)d_in[9],  (const float*)d_in[14] };
    const float* bl[3]  = { (const float*)d_in[5],  (const float*)d_in[10], (const float*)d_in[15] };
    const float* gl[3]  = { (const float*)d_in[6],  (const float*)d_in[11], (const float*)d_in[16] };
    const float* bel[3] = { (const float*)d_in[7],  (const float*)d_in[12], (const float*)d_in[17] };
    const float* P1 = (const float*)d_in[18];
    const float* P2 = (const float*)d_in[19];
    float* out = (float*)d_out;

    void* pA_; void* pB_; void* pDeg_; void* pWhi_; void* pWlo_;
    cudaGetSymbolAddress(&pA_, g_bufA);
    cudaGetSymbolAddress(&pB_, g_bufB);
    cudaGetSymbolAddress(&pDeg_, g_deg);
    cudaGetSymbolAddress(&pWhi_, g_WhiAll);
    cudaGetSymbolAddress(&pWlo_, g_WloAll);
    float* bufA = (float*)pA_;
    float* bufB = (float*)pB_;
    const uint4* whiAll = (const uint4*)pWhi_;
    const uint4* wloAll = (const uint4*)pWlo_;

    static cudaStream_t s1 = nullptr;
    static cudaEvent_t evFork = nullptr, evG0 = nullptr, evM2 = nullptr;
    if (!s1) {
        cudaStreamCreateWithFlags(&s1, cudaStreamNonBlocking);
        cudaEventCreateWithFlags(&evFork, cudaEventDisableTiming);
        cudaEventCreateWithFlags(&evG0, cudaEventDisableTiming);
        cudaEventCreateWithFlags(&evM2, cudaEventDisableTiming);
        cudaFuncSetAttribute(k_gemm_mma<false>, cudaFuncAttributeMaxDynamicSharedMemorySize, SME_TOTAL);
        cudaFuncSetAttribute(k_gemm_mma<true>,  cudaFuncAttributeMaxDynamicSharedMemorySize, SME_TOTAL);
    }

    const int EB = 256;
    const int e2grid = (ET / 2 + EB - 1) / EB;                   // 2 edges/thread
    const int agg_grid = (Nn + 8 * AGG_NPW - 1) / (8 * AGG_NPW); // 1563

    // ---- fork: side stream does W prep + GEMM L0 + decoder M while main builds CSR ----
    cudaMemsetAsync(pDeg_, 0, Nn * sizeof(int), 0);
    cudaEventRecord(evFork, 0);
    cudaStreamWaitEvent(s1, evFork, 0);

    // side stream (submission order keeps gemm0 in the ncu capture slot)
    k_wsplit<<<8, 256, 0, s1>>>(Wl[0], 0);
    k_wsplit<<<8, 256, 0, s1>>>(Wl[1], 1);
    k_wsplit<<<8, 256, 0, s1>>>(Wl[2], 2);
    k_gemm_mma<false><<<GEMM_GRID, 256, SME_TOTAL, s1>>>(
        x, attl[0], nullptr, nullptr, whiAll, wloAll, bufA, Nn);
    cudaEventRecord(evG0, s1);
    k_m2<<<128, 128, 0, s1>>>(P1, P2);
    cudaEventRecord(evM2, s1);

    // main stream: CSR build (by dst)
    k_count<<<e2grid, EB>>>(ei);
    k_scan<<<1, 1024>>>();
    k_scatter<<<e2grid, EB>>>(ei);

    // join: edge L0 needs GEMM L0's si/sj/den
    cudaStreamWaitEvent(0, evG0, 0);

    const float* layer_in = bufB;
    for (int L = 0; L < 3; L++) {
        if (L > 0) {
            k_gemm_mma<true><<<GEMM_GRID, 256, SME_TOTAL>>>(
                layer_in, attl[L], gl[L - 1], bel[L - 1],
                whiAll + L * 2048, wloAll + L * 2048, bufA, Nn);
        }
        k_edge<<<e2grid, EB>>>();
        k_aggregate<<<agg_grid, 256>>>(bufA, bl[L], bufB);
        layer_in = bufB;
    }

    cudaStreamWaitEvent(0, evM2, 0);
    k_decode<<<Bb, 128>>>(bufB, drug, gl[2], bel[2], out);
}

// round 17
// speedup vs baseline: 1.2261x; 1.0110x over previous
#include <cuda_runtime.h>
#include <cuda_bf16.h>
#include <float.h>
#include <math.h>
#include <stdint.h>

// Problem constants (fixed by the reference)
#define Nn 50000
#define Ee 600000
#define ET (Ee + Nn)     // edges + self loops = 650000 (even; Ee even)
#define D  128
#define Bb 1024
#define BN_EPS 1e-5f
#define AGG_NPW 4        // nodes per warp in aggregation
#define TROWS 64         // GEMM tile rows
#define NTILES ((Nn + TROWS - 1) / TROWS)   // 782
#define GEMM_GRID 296    // 2 CTAs/SM x 148 SMs: single balanced wave (2-3 tiles/CTA)

// ---------------- static device scratch ----------------
__device__ float g_bufA[Nn * D];      // GEMM output h (fp32)
__device__ float g_bufB[Nn * D];      // aggregated output
__device__ float g_si[Nn], g_sj[Nn];
__device__ float g_den[Nn];           // sum of exp per src node (raw)
__device__ float g_alpha[ET];         // exp(alpha), CSR-position order
__device__ int   g_srcpos[ET];
__device__ int   g_dstpos[ET];
__device__ int   g_deg[Nn];
__device__ int   g_off[Nn + 1];
__device__ int   g_cur[Nn];
__device__ float g_bnsum[D], g_bnsq[D];
__device__ float g_M[D * D];
// padded-row bf16 split images of W for all 3 layers: [3][2048] uint4 each
__device__ uint4 g_WhiAll[3 * 2048];
__device__ uint4 g_WloAll[3 * 2048];

// ---------------- PTX helpers (plain compute_103-safe) ----------------
__device__ __forceinline__ uint32_t smem_u32(const void* p) {
    uint32_t a;
    asm("{ .reg .u64 t; cvta.to.shared.u64 t, %1; cvt.u32.u64 %0, t; }" : "=r"(a) : "l"(p));
    return a;
}

__device__ __forceinline__ void ldmx4(uint32_t* r, uint32_t addr) {
    asm volatile("ldmatrix.sync.aligned.m8n8.x4.shared.b16 {%0,%1,%2,%3}, [%4];"
                 : "=r"(r[0]), "=r"(r[1]), "=r"(r[2]), "=r"(r[3]) : "r"(addr));
}

__device__ __forceinline__ void mma16816(float* c, const uint32_t* a, uint32_t b0, uint32_t b1) {
    asm volatile(
        "mma.sync.aligned.m16n8k16.row.col.f32.bf16.bf16.f32 "
        "{%0,%1,%2,%3}, {%4,%5,%6,%7}, {%8,%9}, {%0,%1,%2,%3};"
        : "+f"(c[0]), "+f"(c[1]), "+f"(c[2]), "+f"(c[3])
        : "r"(a[0]), "r"(a[1]), "r"(a[2]), "r"(a[3]), "r"(b0), "r"(b1));
}

// ---------------- CSR build (by dst), 2 edges/thread ----------------
__global__ void k_count(const int* __restrict__ ei) {
    int pos = (blockIdx.x * blockDim.x + threadIdx.x) * 2;
    if (pos >= ET) return;
    int d0, d1;
    if (pos < Ee) {
        int2 dd = *(const int2*)(ei + Ee + pos);
        d0 = dd.x; d1 = dd.y;
    } else {
        d0 = pos - Ee; d1 = pos + 1 - Ee;
    }
    atomicAdd(&g_deg[d0], 1);
    atomicAdd(&g_deg[d1], 1);
}

__global__ void k_scan() {
    __shared__ int part[1024];
    int tid = threadIdx.x;
    const int CH = (Nn + 1023) / 1024;
    int base = tid * CH;
    int s = 0;
    for (int i = 0; i < CH; i++) {
        int idx = base + i;
        if (idx < Nn) s += g_deg[idx];
    }
    part[tid] = s;
    __syncthreads();
    for (int d = 1; d < 1024; d <<= 1) {
        int v = (tid >= d) ? part[tid - d] : 0;
        __syncthreads();
        part[tid] += v;
        __syncthreads();
    }
    int run = (tid > 0) ? part[tid - 1] : 0;
    for (int i = 0; i < CH; i++) {
        int idx = base + i;
        if (idx < Nn) {
            g_off[idx] = run;
            g_cur[idx] = run;
            run += g_deg[idx];
        }
    }
    if (tid == 1023) g_off[Nn] = part[1023];
}

__global__ void k_scatter(const int* __restrict__ ei) {
    int pos = (blockIdx.x * blockDim.x + threadIdx.x) * 2;
    if (pos >= ET) return;
    int s0, s1, d0, d1;
    if (pos < Ee) {
        int2 ss = *(const int2*)(ei + pos);
        int2 dd = *(const int2*)(ei + Ee + pos);
        s0 = ss.x; s1 = ss.y; d0 = dd.x; d1 = dd.y;
    } else {
        s0 = pos - Ee; s1 = pos + 1 - Ee;
        d0 = s0; d1 = s1;
    }
    int p0 = atomicAdd(&g_cur[d0], 1);
    g_srcpos[p0] = s0;
    g_dstpos[p0] = d0;
    int p1 = atomicAdd(&g_cur[d1], 1);
    g_srcpos[p1] = s1;
    g_dstpos[p1] = d1;
}

#define SROW 272

// ---------------- W split: fp32 -> padded-row bf16 hi/lo images (one layer) ----------
__global__ void k_wsplit(const float* __restrict__ W, int L) {
    int idx = blockIdx.x * blockDim.x + threadIdx.x;  // 0..2047
    if (idx >= 2048) return;
    int n = idx >> 4;           // row (out channel)
    int k0 = (idx & 15) * 8;    // 8 consecutive k
    const float* src = W + n * 128 + k0;
    float v[8];
#pragma unroll
    for (int j = 0; j < 8; j++) v[j] = src[j];
    uint32_t hi[4], lo[4];
#pragma unroll
    for (int j = 0; j < 4; j++) {
        __nv_bfloat162 hp = __floats2bfloat162_rn(v[2 * j], v[2 * j + 1]);
        float2 hf = __bfloat1622float2(hp);
        __nv_bfloat162 lp = __floats2bfloat162_rn(v[2 * j] - hf.x, v[2 * j + 1] - hf.y);
        hi[j] = *reinterpret_cast<uint32_t*>(&hp);
        lo[j] = *reinterpret_cast<uint32_t*>(&lp);
    }
    g_WhiAll[L * 2048 + idx] = make_uint4(hi[0], hi[1], hi[2], hi[3]);
    g_WloAll[L * 2048 + idx] = make_uint4(lo[0], lo[1], lo[2], lo[3]);
}

// ---------------- HMMA GEMM: C = A' @ W^T, persistent tiles, 2 CTAs/SM ----------------
#define SME_ATT  0
#define SME_SC   1024
#define SME_SH   1536
#define SME_REDI 2048
#define SME_REDJ 3072
#define SME_AHI  4096
#define SME_ALO  (SME_AHI + TROWS * SROW)
#define SME_WHI  (SME_ALO + TROWS * SROW)
#define SME_WLO  (SME_WHI + 128 * SROW)
#define SME_TOTAL (SME_WLO + 128 * SROW)   // 108544 B -> 2 CTAs/SM

template <bool BN>
__global__ void __launch_bounds__(256, 2)
k_gemm_mma(const float* __restrict__ A, const float* __restrict__ att,
           const float* __restrict__ gamma, const float* __restrict__ beta,
           const uint4* __restrict__ whiG, const uint4* __restrict__ wloG,
           float* __restrict__ C, int Mrows) {
    extern __shared__ char smem[];
    uint32_t sb = smem_u32(smem);
    int tid = threadIdx.x;
    int wid = tid >> 5;
    int lane = tid & 31;
    int warpM = wid & 1;   // 0..1, 32 rows each
    int warpN = wid >> 1;  // 0..3, 32 cols each

    float* attS = (float*)(smem + SME_ATT);
    float* scS  = (float*)(smem + SME_SC);
    float* shS  = (float*)(smem + SME_SH);
    float* redI = (float*)(smem + SME_REDI);
    float* redJ = (float*)(smem + SME_REDJ);

    if (tid < 256) attS[tid] = att[tid];
    if (BN && tid < 128) {
        const float invN = 1.f / (float)Nn;
        float mu = g_bnsum[tid] * invN;
        float var = g_bnsq[tid] * invN - mu * mu;
        float sc = rsqrtf(var + BN_EPS) * gamma[tid];
        scS[tid] = sc;
        shS[tid] = beta[tid] - mu * sc;
    }

    // copy padded W images into smem (once per CTA, reused across tiles)
    for (int i = tid; i < 2048; i += 256) {
        int r = i >> 4;
        int c = i & 15;
        *(uint4*)(smem + SME_WHI + r * SROW + c * 16) = whiG[i];
        *(uint4*)(smem + SME_WLO + r * SROW + c * 16) = wloG[i];
    }
    __syncthreads();   // W + BN coefficients ready

    // lane-invariant addressing
    int a_row = lane & 15;
    int a_k   = (lane >> 4) * 8;
    uint32_t aLaneOff = a_row * SROW + a_k * 2;
    int b_n = (lane & 7) + ((lane >> 4) << 3);
    int b_k = ((lane >> 3) & 1) * 8;
    uint32_t bLaneOff = b_n * SROW + b_k * 2;
    uint32_t aBaseHi = sb + SME_AHI + (warpM * 32) * SROW + aLaneOff;
    uint32_t aBaseLo = sb + SME_ALO + (warpM * 32) * SROW + aLaneOff;
    uint32_t bBaseH  = sb + SME_WHI + (warpN * 32) * SROW + bLaneOff;
    uint32_t bBaseL  = sb + SME_WLO + (warpN * 32) * SROW + bLaneOff;

    for (int tile = blockIdx.x; tile < NTILES; tile += gridDim.x) {
        int block_row = tile * TROWS;

        // convert A tile (64 rows) -> bf16 hi/lo (padded rows)
        {
            int r = tid >> 2;               // 0..63
            int kq = (tid & 3) * 32;        // quarter-row
            int grow = block_row + r;
            bool valid = (grow < Mrows);
            const float* arow = A + (size_t)grow * 128 + kq;
#pragma unroll
            for (int c = 0; c < 4; c++) {   // 4 chunks of 8 floats
                int k0 = kq + c * 8;
                float v[8];
                if (valid) {
                    float4 p0 = *(const float4*)(arow + c * 8);
                    float4 p1 = *(const float4*)(arow + c * 8 + 4);
                    v[0] = p0.x; v[1] = p0.y; v[2] = p0.z; v[3] = p0.w;
                    v[4] = p1.x; v[5] = p1.y; v[6] = p1.z; v[7] = p1.w;
                } else {
#pragma unroll
                    for (int j = 0; j < 8; j++) v[j] = 0.f;
                }
                if (BN) {
#pragma unroll
                    for (int j = 0; j < 8; j++) {
                        float y = v[j] * scS[k0 + j] + shS[k0 + j];
                        v[j] = (y > 0.f) ? y : 0.1f * y;
                    }
                }
                uint32_t hi[4], lo[4];
#pragma unroll
                for (int j = 0; j < 4; j++) {
                    __nv_bfloat162 hp = __floats2bfloat162_rn(v[2 * j], v[2 * j + 1]);
                    float2 hf = __bfloat1622float2(hp);
                    __nv_bfloat162 lp = __floats2bfloat162_rn(v[2 * j] - hf.x, v[2 * j + 1] - hf.y);
                    hi[j] = *reinterpret_cast<uint32_t*>(&hp);
                    lo[j] = *reinterpret_cast<uint32_t*>(&lp);
                }
                *(uint4*)(smem + SME_AHI + r * SROW + k0 * 2) = make_uint4(hi[0], hi[1], hi[2], hi[3]);
                *(uint4*)(smem + SME_ALO + r * SROW + k0 * 2) = make_uint4(lo[0], lo[1], lo[2], lo[3]);
            }
        }
        __syncthreads();

        // ---- MMA mainloop: fused hi-phase then lo-phase ----
        float acc[2][4][4];
#pragma unroll
        for (int mf = 0; mf < 2; mf++)
#pragma unroll
            for (int nf = 0; nf < 4; nf++)
#pragma unroll
                for (int q = 0; q < 4; q++) acc[mf][nf][q] = 0.f;

#pragma unroll
        for (int ks = 0; ks < 8; ks++) {
            uint32_t kb = ks * 32;
            uint32_t afrag[2][4];
            ldmx4(afrag[0], aBaseHi + kb);
            ldmx4(afrag[1], aBaseHi + 16 * SROW + kb);
            uint32_t bh[2][4], bl[2][4];
            ldmx4(bh[0], bBaseH + kb);
            ldmx4(bh[1], bBaseH + 16 * SROW + kb);
            ldmx4(bl[0], bBaseL + kb);
            ldmx4(bl[1], bBaseL + 16 * SROW + kb);
#pragma unroll
            for (int mf = 0; mf < 2; mf++)
#pragma unroll
                for (int nf = 0; nf < 4; nf++) {
                    mma16816(acc[mf][nf], afrag[mf],
                             bh[nf >> 1][(nf & 1) * 2], bh[nf >> 1][(nf & 1) * 2 + 1]);
                    mma16816(acc[mf][nf], afrag[mf],
                             bl[nf >> 1][(nf & 1) * 2], bl[nf >> 1][(nf & 1) * 2 + 1]);
                }
        }
#pragma unroll
        for (int ks = 0; ks < 8; ks++) {
            uint32_t kb = ks * 32;
            uint32_t afrag[2][4];
            ldmx4(afrag[0], aBaseLo + kb);
            ldmx4(afrag[1], aBaseLo + 16 * SROW + kb);
            uint32_t bh[2][4];
            ldmx4(bh[0], bBaseH + kb);
            ldmx4(bh[1], bBaseH + 16 * SROW + kb);
#pragma unroll
            for (int mf = 0; mf < 2; mf++)
#pragma unroll
                for (int nf = 0; nf < 4; nf++)
                    mma16816(acc[mf][nf], afrag[mf],
                             bh[nf >> 1][(nf & 1) * 2], bh[nf >> 1][(nf & 1) * 2 + 1]);
        }

        // ---- epilogue: store C + fused si/sj ----
        int qrow = lane >> 2;
        int qcol = (lane & 3) * 2;
        float pi[4] = {0.f, 0.f, 0.f, 0.f};
        float pj[4] = {0.f, 0.f, 0.f, 0.f};
#pragma unroll
        for (int mf = 0; mf < 2; mf++) {
#pragma unroll
            for (int half = 0; half < 2; half++) {
                int rloc = warpM * 32 + mf * 16 + half * 8 + qrow;
                int grow = block_row + rloc;
                float rpi = 0.f, rpj = 0.f;
#pragma unroll
                for (int nf = 0; nf < 4; nf++) {
                    int col = warpN * 32 + nf * 8 + qcol;
                    float c0 = acc[mf][nf][half * 2 + 0];
                    float c1 = acc[mf][nf][half * 2 + 1];
                    rpi = fmaf(c0, attS[col], rpi);
                    rpi = fmaf(c1, attS[col + 1], rpi);
                    rpj = fmaf(c0, attS[128 + col], rpj);
                    rpj = fmaf(c1, attS[128 + col + 1], rpj);
                    if (grow < Mrows)
                        *(float2*)(C + (size_t)grow * 128 + col) = make_float2(c0, c1);
                }
                pi[mf * 2 + half] = rpi;
                pj[mf * 2 + half] = rpj;
            }
        }
#pragma unroll
        for (int off = 1; off < 4; off <<= 1) {
#pragma unroll
            for (int q = 0; q < 4; q++) {
                pi[q] += __shfl_xor_sync(0xffffffffu, pi[q], off);
                pj[q] += __shfl_xor_sync(0xffffffffu, pj[q], off);
            }
        }
        if ((lane & 3) == 0) {
#pragma unroll
            for (int mf = 0; mf < 2; mf++)
#pragma unroll
                for (int half = 0; half < 2; half++) {
                    int rloc = warpM * 32 + mf * 16 + half * 8 + qrow;
                    redI[warpN * 64 + rloc] = pi[mf * 2 + half];
                    redJ[warpN * 64 + rloc] = pj[mf * 2 + half];
                }
        }
        __syncthreads();
        if (tid < TROWS) {
            int grow = block_row + tid;
            if (grow < Mrows) {
                g_si[grow] = (redI[tid] + redI[64 + tid]) + (redI[128 + tid] + redI[192 + tid]);
                g_sj[grow] = (redJ[tid] + redJ[64 + tid]) + (redJ[128 + tid] + redJ[192 + tid]);
                g_den[grow] = 0.f;
            }
        }
        __syncthreads();
    }
}

// ---------------- edge pass: 2 edges/thread, leaky + exp + den atomics ----------------
// block 0 also zeroes the BN accumulators (after GEMM L consumed them, before agg L)
__global__ void k_edge() {
    if (blockIdx.x == 0 && threadIdx.x < 128) {
        g_bnsum[threadIdx.x] = 0.f;
        g_bnsq[threadIdx.x] = 0.f;
    }
    int pos = (blockIdx.x * blockDim.x + threadIdx.x) * 2;
    if (pos >= ET) return;
    int2 ss = *(const int2*)(g_srcpos + pos);
    int2 dd = *(const int2*)(g_dstpos + pos);
    float a0 = g_si[dd.x] + g_sj[ss.x];
    float a1 = g_si[dd.y] + g_sj[ss.y];
    a0 = (a0 > 0.f) ? a0 : 0.2f * a0;   // NEG_GAT
    a1 = (a1 > 0.f) ? a1 : 0.2f * a1;
    float e0 = __expf(a0);
    float e1 = __expf(a1);
    *(float2*)(g_alpha + pos) = make_float2(e0, e1);
    atomicAdd(&g_den[ss.x], e0);
    atomicAdd(&g_den[ss.y], e1);
}

// ---------------- aggregation: warp-per-node (x AGG_NPW), float4 lanes (R14 form) ----
__global__ void __launch_bounds__(256)
k_aggregate(const float* __restrict__ h, const float* __restrict__ bias,
            float* __restrict__ out) {
    __shared__ float sB[8][128];
    __shared__ float sQ[8][128];
    int lane = threadIdx.x & 31;
    int w = threadIdx.x >> 5;    // warp in block 0..7
    int v0 = (blockIdx.x * 8 + w) * AGG_NPW;
    int c4 = lane * 4;
    float4 bi = *(const float4*)(bias + c4);
    float4 bsum = make_float4(0.f, 0.f, 0.f, 0.f);
    float4 bsq  = make_float4(0.f, 0.f, 0.f, 0.f);
#pragma unroll
    for (int n = 0; n < AGG_NPW; n++) {
        int v = v0 + n;
        if (v >= Nn) break;
        int s = g_off[v];
        int e = g_off[v + 1];
        float4 a0 = make_float4(0.f, 0.f, 0.f, 0.f);
        float4 a1 = make_float4(0.f, 0.f, 0.f, 0.f);
        int i = s;
        for (; i + 1 < e; i += 2) {
            int s0 = g_srcpos[i];
            int s1 = g_srcpos[i + 1];
            float w0 = __fdividef(g_alpha[i], g_den[s0] + 1e-16f);
            float w1 = __fdividef(g_alpha[i + 1], g_den[s1] + 1e-16f);
            float4 h0 = *(const float4*)(h + (size_t)s0 * 128 + c4);
            float4 h1 = *(const float4*)(h + (size_t)s1 * 128 + c4);
            a0.x = fmaf(w0, h0.x, a0.x); a0.y = fmaf(w0, h0.y, a0.y);
            a0.z = fmaf(w0, h0.z, a0.z); a0.w = fmaf(w0, h0.w, a0.w);
            a1.x = fmaf(w1, h1.x, a1.x); a1.y = fmaf(w1, h1.y, a1.y);
            a1.z = fmaf(w1, h1.z, a1.z); a1.w = fmaf(w1, h1.w, a1.w);
        }
        if (i < e) {
            int s0 = g_srcpos[i];
            float w0 = __fdividef(g_alpha[i], g_den[s0] + 1e-16f);
            float4 h0 = *(const float4*)(h + (size_t)s0 * 128 + c4);
            a0.x = fmaf(w0, h0.x, a0.x); a0.y = fmaf(w0, h0.y, a0.y);
            a0.z = fmaf(w0, h0.z, a0.z); a0.w = fmaf(w0, h0.w, a0.w);
        }
        float4 u;
        u.x = a0.x + a1.x + bi.x; u.y = a0.y + a1.y + bi.y;
        u.z = a0.z + a1.z + bi.z; u.w = a0.w + a1.w + bi.w;
        u.x = (u.x > 0.f) ? u.x : 0.f;
        u.y = (u.y > 0.f) ? u.y : 0.f;
        u.z = (u.z > 0.f) ? u.z : 0.f;
        u.w = (u.w > 0.f) ? u.w : 0.f;
        *(float4*)(out + (size_t)v * 128 + c4) = u;
        bsum.x += u.x; bsum.y += u.y; bsum.z += u.z; bsum.w += u.w;
        bsq.x = fmaf(u.x, u.x, bsq.x); bsq.y = fmaf(u.y, u.y, bsq.y);
        bsq.z = fmaf(u.z, u.z, bsq.z); bsq.w = fmaf(u.w, u.w, bsq.w);
    }
    *(float4*)&sB[w][c4] = bsum;
    *(float4*)&sQ[w][c4] = bsq;
    __syncthreads();
    int c = threadIdx.x;
    if (c < 128) {
        float ssum = 0.f, ssq = 0.f;
#pragma unroll
        for (int ww = 0; ww < 8; ww++) {
            ssum += sB[ww][c];
            ssq  += sQ[ww][c];
        }
        atomicAdd(&g_bnsum[c], ssum);
        atomicAdd(&g_bnsq[c], ssq);
    }
}

// ---------------- decoder: M = P1 @ P2 @ P1^T ----------------
__global__ void k_m2(const float* __restrict__ P1, const float* __restrict__ P2) {
    __shared__ float p1r[64];
    __shared__ float qrow[64];
    int r = blockIdx.x;
    int t = threadIdx.x;
    if (t < 64) p1r[t] = P1[r * 64 + t];
    __syncthreads();
    if (t < 64) {
        float a0 = 0.f, a1 = 0.f, a2 = 0.f, a3 = 0.f;
#pragma unroll
        for (int k = 0; k < 64; k += 4) {
            a0 = fmaf(p1r[k + 0], P2[(k + 0) * 64 + t], a0);
            a1 = fmaf(p1r[k + 1], P2[(k + 1) * 64 + t], a1);
            a2 = fmaf(p1r[k + 2], P2[(k + 2) * 64 + t], a2);
            a3 = fmaf(p1r[k + 3], P2[(k + 3) * 64 + t], a3);
        }
        qrow[t] = (a0 + a1) + (a2 + a3);
    }
    __syncthreads();
    float a0 = 0.f, a1 = 0.f, a2 = 0.f, a3 = 0.f;
#pragma unroll
    for (int k = 0; k < 64; k += 4) {
        a0 = fmaf(qrow[k + 0], P1[t * 64 + k + 0], a0);
        a1 = fmaf(qrow[k + 1], P1[t * 64 + k + 1], a1);
        a2 = fmaf(qrow[k + 2], P1[t * 64 + k + 2], a2);
        a3 = fmaf(qrow[k + 3], P1[t * 64 + k + 3], a3);
    }
    g_M[r * 128 + t] = (a0 + a1) + (a2 + a3);
}

// ---------------- decoder: ypred = a^T M b (BN+leaky inline) ----------------
__global__ void k_decode(const float* __restrict__ h, const int* __restrict__ drug,
                         const float* __restrict__ gamma, const float* __restrict__ beta,
                         float* __restrict__ out) {
    __shared__ float ash[128];
    __shared__ float bsh[128];
    __shared__ float wsum[4];
    int b = blockIdx.x;
    int t = threadIdx.x;
    int ia = drug[b * 2 + 0] - 1;
    int ib = drug[b * 2 + 1] - 1;
    const float invN = 1.f / (float)Nn;
    float mu = g_bnsum[t] * invN;
    float var = g_bnsq[t] * invN - mu * mu;
    float sc = rsqrtf(var + BN_EPS) * gamma[t];
    float sh = beta[t] - mu * sc;
    float ya = h[(size_t)ia * 128 + t] * sc + sh;
    float yb = h[(size_t)ib * 128 + t] * sc + sh;
    ash[t] = (ya > 0.f) ? ya : 0.1f * ya;
    bsh[t] = (yb > 0.f) ? yb : 0.1f * yb;
    __syncthreads();
    float acc = 0.f;
#pragma unroll 8
    for (int d = 0; d < 128; d++) acc = fmaf(ash[d], g_M[d * 128 + t], acc);
    float val = acc * bsh[t];
#pragma unroll
    for (int o = 16; o > 0; o >>= 1) val += __shfl_down_sync(0xffffffffu, val, o);
    if ((t & 31) == 0) wsum[t >> 5] = val;
    __syncthreads();
    if (t == 0) out[b] = wsum[0] + wsum[1] + wsum[2] + wsum[3];
}

// ---------------- launch ----------------
extern "C" void kernel_launch(void* const* d_in, const int* in_sizes, int n_in,
                              void* d_out, int out_size) {
    const float* x    = (const float*)d_in[0];
    const int*   ei   = (const int*)d_in[1];
    const int*   drug = (const int*)d_in[2];
    const float* Wl[3]  = { (const float*)d_in[3],  (const float*)d_in[8],  (const float*)d_in[13] };
    const float* attl[3]= { (const float*)d_in[4],  (const float*)d_in[9],  (const float*)d_in[14] };
    const float* bl[3]  = { (const float*)d_in[5],  (const float*)d_in[10], (const float*)d_in[15] };
    const float* gl[3]  = { (const float*)d_in[6],  (const float*)d_in[11], (const float*)d_in[16] };
    const float* bel[3] = { (const float*)d_in[7],  (const float*)d_in[12], (const float*)d_in[17] };
    const float* P1 = (const float*)d_in[18];
    const float* P2 = (const float*)d_in[19];
    float* out = (float*)d_out;

    void* pA_; void* pB_; void* pDeg_; void* pWhi_; void* pWlo_;
    cudaGetSymbolAddress(&pA_, g_bufA);
    cudaGetSymbolAddress(&pB_, g_bufB);
    cudaGetSymbolAddress(&pDeg_, g_deg);
    cudaGetSymbolAddress(&pWhi_, g_WhiAll);
    cudaGetSymbolAddress(&pWlo_, g_WloAll);
    float* bufA = (float*)pA_;
    float* bufB = (float*)pB_;
    const uint4* whiAll = (const uint4*)pWhi_;
    const uint4* wloAll = (const uint4*)pWlo_;

    static cudaStream_t s1 = nullptr;
    static cudaEvent_t evFork = nullptr, evG0 = nullptr, evM2 = nullptr;
    if (!s1) {
        cudaStreamCreateWithFlags(&s1, cudaStreamNonBlocking);
        cudaEventCreateWithFlags(&evFork, cudaEventDisableTiming);
        cudaEventCreateWithFlags(&evG0, cudaEventDisableTiming);
        cudaEventCreateWithFlags(&evM2, cudaEventDisableTiming);
        cudaFuncSetAttribute(k_gemm_mma<false>, cudaFuncAttributeMaxDynamicSharedMemorySize, SME_TOTAL);
        cudaFuncSetAttribute(k_gemm_mma<true>,  cudaFuncAttributeMaxDynamicSharedMemorySize, SME_TOTAL);
    }

    const int EB = 256;
    const int e2grid = (ET / 2 + EB - 1) / EB;                   // 2 edges/thread
    const int agg_grid = (Nn + 8 * AGG_NPW - 1) / (8 * AGG_NPW); // 1563

    // ---- fork: side stream does W prep + GEMM L0 + decoder M while main builds CSR ----
    cudaMemsetAsync(pDeg_, 0, Nn * sizeof(int), 0);
    cudaEventRecord(evFork, 0);
    cudaStreamWaitEvent(s1, evFork, 0);

    // side stream (submission order keeps gemm0 in the ncu capture slot)
    k_wsplit<<<8, 256, 0, s1>>>(Wl[0], 0);
    k_wsplit<<<8, 256, 0, s1>>>(Wl[1], 1);
    k_wsplit<<<8, 256, 0, s1>>>(Wl[2], 2);
    k_gemm_mma<false><<<GEMM_GRID, 256, SME_TOTAL, s1>>>(
        x, attl[0], nullptr, nullptr, whiAll, wloAll, bufA, Nn);
    cudaEventRecord(evG0, s1);
    k_m2<<<128, 128, 0, s1>>>(P1, P2);
    cudaEventRecord(evM2, s1);

    // main stream: CSR build (by dst)
    k_count<<<e2grid, EB>>>(ei);
    k_scan<<<1, 1024>>>();
    k_scatter<<<e2grid, EB>>>(ei);

    // join: edge L0 needs GEMM L0's si/sj/den
    cudaStreamWaitEvent(0, evG0, 0);

    const float* layer_in = bufB;
    for (int L = 0; L < 3; L++) {
        if (L > 0) {
            k_gemm_mma<true><<<GEMM_GRID, 256, SME_TOTAL>>>(
                layer_in, attl[L], gl[L - 1], bel[L - 1],
                whiAll + L * 2048, wloAll + L * 2048, bufA, Nn);
        }
        k_edge<<<e2grid, EB>>>();
        k_aggregate<<<agg_grid, 256>>>(bufA, bl[L], bufB);
        layer_in = bufB;
    }

    cudaStreamWaitEvent(0, evM2, 0);
    k_decode<<<Bb, 128>>>(bufB, drug, gl[2], bel[2], out);
}